// round 2
// baseline (speedup 1.0000x reference)
#include <cuda_runtime.h>
#include <math.h>

#define Bdim 4
#define Sdim 512
#define Kdim 32
#define Vdim 32000
#define ROWS (Bdim * Sdim)   /* 2048 */
#define NTHREADS 256
#define V4 (Vdim / 4)        /* 8000 */

__device__ __forceinline__ float warp_sum(float v) {
#pragma unroll
    for (int o = 16; o > 0; o >>= 1) v += __shfl_xor_sync(0xffffffffu, v, o);
    return v;
}
__device__ __forceinline__ float warp_max(float v) {
#pragma unroll
    for (int o = 16; o > 0; o >>= 1) v = fmaxf(v, __shfl_xor_sync(0xffffffffu, v, o));
    return v;
}

// Insert v into a descending-sorted 8-element register list.
__device__ __forceinline__ void ins8(float (&t)[8], float v) {
    if (v <= t[7]) return;     // common case: one compare, no divergent work
    t[7] = v;
#pragma unroll
    for (int i = 7; i > 0; --i) {
        if (t[i] > t[i - 1]) { float tmp = t[i - 1]; t[i - 1] = t[i]; t[i] = tmp; }
    }
}

__global__ __launch_bounds__(NTHREADS)
void robust_combiner_kernel(const int*   __restrict__ tgt,
                            const float* __restrict__ dists,
                            const float* __restrict__ keyf,
                            const float* __restrict__ nprobs,
                            const float* __restrict__ selp,
                            const float* __restrict__ Wf,  const float* __restrict__ bf,
                            const float* __restrict__ W1a, const float* __restrict__ b1a,
                            const float* __restrict__ W1b, const float* __restrict__ b1b,
                            const float* __restrict__ W2a, const float* __restrict__ b2a,
                            const float* __restrict__ W2b, const float* __restrict__ b2b,
                            float* __restrict__ out)
{
    const int row = blockIdx.x;
    const int tid = threadIdx.x;

    __shared__ float s_top[NTHREADS][8];
    __shared__ float s_d[Kdim], s_lk[Kdim], s_ls[Kdim], s_cnt[Kdim], s_p[Kdim];
    __shared__ int   s_t[Kdim];

    const float4* __restrict__ in4  = reinterpret_cast<const float4*>(nprobs) + (size_t)row * V4;
    float4*       __restrict__ out4 = reinterpret_cast<float4*>(out)          + (size_t)row * V4;
    const float4 z4 = make_float4(0.f, 0.f, 0.f, 0.f);

    // ---- Phase A: fused stream — read probs row (top-8 scan) + zero output row ----
    float t8[8];
#pragma unroll
    for (int i = 0; i < 8; i++) t8[i] = -1.0f;  // probs > 0, safe sentinel

    for (int i = tid; i < V4; i += NTHREADS) {
        float4 v = __ldcs(&in4[i]);             // evict-first: no reuse of this stream
        ins8(t8, v.x); ins8(t8, v.y); ins8(t8, v.z); ins8(t8, v.w);
        __stcs(&out4[i], z4);                   // streaming zero-fill
    }

#pragma unroll
    for (int i = 0; i < 8; i++) s_top[tid][i] = t8[i];
    __syncthreads();

    // ---- Phase B: tree merge of 256 sorted top-8 lists ----
    for (int off = NTHREADS / 2; off >= 1; off >>= 1) {
        if (tid < off) {
            float a[8], b[8], m[8];
#pragma unroll
            for (int i = 0; i < 8; i++) { a[i] = s_top[tid][i]; b[i] = s_top[tid + off][i]; }
            int ia = 0, ib = 0;
#pragma unroll
            for (int k = 0; k < 8; k++) {   // ia+ib==k<8, both indices stay in range
                float av = a[ia], bv = b[ib];
                if (av >= bv) { m[k] = av; ia++; } else { m[k] = bv; ib++; }
            }
#pragma unroll
            for (int i = 0; i < 8; i++) s_top[tid][i] = m[i];
        }
        __syncthreads();
    }
    // s_top[0][0..7] = row top-8, descending (matches jax.lax.top_k order)

    // ---- Phase C: per-row scalar math on warp 0 (one lane per k) ----
    if (tid < Kdim) {
        const int k = tid;
        const size_t base = (size_t)row * Kdim;

        int   tv = tgt[base + k];
        float d  = dists[base + k];
        float lk = logf(keyf[base + k]);
        float ls = logf(selp[base + k]);
        s_t[k] = tv; s_d[k] = d; s_lk[k] = lk; s_ls[k] = ls;

        // noise_logit: Linear(2->4) -> tanh -> Linear(4->1)
        float nz = b1b[0];
#pragma unroll
        for (int i = 0; i < 4; i++) {
            float h = tanhf(W1a[2 * i] * lk + W1a[2 * i + 1] * ls + b1a[i]);
            nz += W1b[i] * h;
        }
        __syncwarp();

        // label_counts[k]: distinct NONZERO labels in prefix [0..k]
        // (label 0 never counts: dedup multiplies it to 0 in the reference)
        int cnt = 0;
        for (int i = 0; i <= k; i++) {
            int vi = s_t[i];
            if (vi == 0) continue;
            bool dup = false;
            for (int j = 0; j < i; j++) if (s_t[j] == vi) { dup = true; break; }
            if (!dup) cnt++;
        }
        s_cnt[k] = (float)cnt;
        __syncwarp();

        // fc2 hidden unit k: tanh(W2a[k] . [dists(32), counts(32)] + b2a[k])
        float acc = b2a[k];
        const float* wrow = W2a + k * (2 * Kdim);
#pragma unroll
        for (int i = 0; i < Kdim; i++) acc += wrow[i] * s_d[i];
#pragma unroll
        for (int i = 0; i < Kdim; i++) acc += wrow[Kdim + i] * s_cnt[i];
        float h = tanhf(acc);

        // lambda_logit = W2b @ h + b2b  (butterfly -> all lanes hold the sums)
        float l0 = warp_sum(W2b[k] * h)        + b2b[0];
        float l1 = warp_sum(W2b[Kdim + k] * h) + b2b[1];

        // sim_lambda = W_func . [log(top8)(8), log_key(32), log_sel(32)] + b_func
        float part = Wf[8 + k] * lk + Wf[40 + k] * ls;
        if (k < 8) part += Wf[k] * logf(s_top[0][k]);
        float sim = warp_sum(part) + bf[0];

        // knn_lambda = softmax([l0, sim])[0] = sigmoid(l0 - sim)
        float lam   = 1.0f / (1.0f + expf(sim - l0));
        float tempe = 1.0f / (1.0f + expf(-l1));   // sigmoid(l1)

        // probs = softmax(-dists*tempe + noise) over K
        float logit = -d * tempe + nz;
        float mx = warp_max(logit);
        float e  = expf(logit - mx);
        float se = warp_sum(e);
        s_p[k] = e / se;
        __syncwarp();

        if (k == 0) {
            out[(size_t)Vdim * ROWS + row] = lam;
            // serial in-order scatter: last write wins on duplicate indices
            float* orow = out + (size_t)row * Vdim;
            for (int i = 0; i < Kdim; i++) orow[s_t[i]] = s_p[i];
        }
    }
}

extern "C" void kernel_launch(void* const* d_in, const int* in_sizes, int n_in,
                              void* d_out, int out_size) {
    const int*   tgt    = (const int*)  d_in[0];   // tgt_index [B,S,K] int32
    const float* dists  = (const float*)d_in[1];   // knn_dists [B,S,K]
    const float* keyf   = (const float*)d_in[2];   // knn_key_feature [B,S,K]
    const float* nprobs = (const float*)d_in[3];   // network_probs [B,S,V]
    const float* selp   = (const float*)d_in[4];   // network_select_probs [B,S,K]
    const float* Wf     = (const float*)d_in[5];   // W_func [1, 2K+8]
    const float* bf     = (const float*)d_in[6];   // b_func [1]
    const float* W1a    = (const float*)d_in[7];   // [4,2]
    const float* b1a    = (const float*)d_in[8];   // [4]
    const float* W1b    = (const float*)d_in[9];   // [1,4]
    const float* b1b    = (const float*)d_in[10];  // [1]
    const float* W2a    = (const float*)d_in[11];  // [32,64]
    const float* b2a    = (const float*)d_in[12];  // [32]
    const float* W2b    = (const float*)d_in[13];  // [2,32]
    const float* b2b    = (const float*)d_in[14];  // [2]
    float* out = (float*)d_out;                    // [B*S*V] knn_prob ++ [B*S] knn_lambda

    robust_combiner_kernel<<<ROWS, NTHREADS>>>(
        tgt, dists, keyf, nprobs, selp,
        Wf, bf, W1a, b1a, W1b, b1b, W2a, b2a, W2b, b2b, out);
}